// round 14
// baseline (speedup 1.0000x reference)
#include <cuda_runtime.h>
#include <cuda_bf16.h>
#include <mma.h>
#include <cstdint>

using namespace nvcuda;

// ---------------------------------------------------------------------------
// SCM_MLP: 4 chained layers  out = relu(out @ (W*mask)^T + exp(mu+sig*z)),
// activations concatenated into d_out [B, 4H].
//
// wmma/mma.sync bf16 (family-generic ISA, survives compute_103 target),
// 3-term Markidis split  A*W ~= Ahi*Whi + Ahi*Wlo + Alo*Whi, fp32 accum.
// R13: FOUR 128-thread CTAs per SM (64x64 tiles) -- same 16 warps/SM the
// register file allows, but 4 independent barrier domains instead of 2, so
// sync/load bubbles of one CTA are covered by three siblings. Inner loop is
// R8's proven order: load kt+1 -> commit -> wait1 -> sync -> compute -> sync,
// LDSR=40 padded (conflict-free ldsm, 16B-aligned cp.async).
// ---------------------------------------------------------------------------

static constexpr int NL = 4, NB = 4096, NH = 4096;
static constexpr int BM = 64, BN = 64, BK = 32, STAGES = 2;
static constexpr int NKT = NH / BK;            // 128 k-tiles
static constexpr int LDSR = 40;                // smem row stride in bf16 (80 B)
static constexpr int T_ROWS = 4 * 64;          // Ahi,Alo,Whi,Wlo rows per stage
static constexpr int STAGE_E = T_ROWS * LDSR;  // 10240 els = 20480 B
static constexpr int SMEM_BYTES = STAGES * STAGE_E * 2;  // 40960 B per CTA
static constexpr int OFF_AL = 64 * LDSR;       // 2560
static constexpr int OFF_WH = 128 * LDSR;      // 5120
static constexpr int OFF_WL = 192 * LDSR;      // 7680
static constexpr int FB_LD = 68;               // fp32 epilogue buffer stride
static constexpr int NTHR = 128;

// ------------------------- device scratch (.bss) ---------------------------
__device__ char g_whi[(size_t)NL * NH * NH * 2];   // 128 MiB bf16 hi
__device__ char g_wlo[(size_t)NL * NH * NH * 2];   // 128 MiB bf16 lo
__device__ char g_ahi[2][(size_t)NB * NH * 2];     // ping-pong activations hi
__device__ char g_alo[2][(size_t)NB * NH * 2];     // ping-pong activations lo

// ------------------------------ helpers ------------------------------------
__device__ __forceinline__ void cp16(void* s, const void* g) {
    uint32_t sa = (uint32_t)__cvta_generic_to_shared(s);
    asm volatile("cp.async.cg.shared.global [%0], [%1], 16;" :: "r"(sa), "l"(g));
}
#define CP_COMMIT() asm volatile("cp.async.commit_group;" ::: "memory")
#define CP_WAIT1()  asm volatile("cp.async.wait_group 1;" ::: "memory")

__device__ __forceinline__ uint32_t pack2(__nv_bfloat16 a, __nv_bfloat16 b) {
    __nv_bfloat162 t(a, b);
    return *reinterpret_cast<uint32_t*>(&t);
}

// ---------------------------------------------------------------------------
// Prepass: split W*mask into bf16 hi/lo (row-major [L][N][K]).
// ---------------------------------------------------------------------------
__global__ void wsplit_kernel(const float* __restrict__ w, const float* __restrict__ m) {
    size_t e = ((size_t)blockIdx.x * 256u + threadIdx.x) * 2u;
    float2 wv = *(const float2*)(w + e);
    float2 mv = *(const float2*)(m + e);
    float v0 = wv.x * mv.x, v1 = wv.y * mv.y;
    __nv_bfloat16 h0 = __float2bfloat16(v0), h1 = __float2bfloat16(v1);
    float l0 = v0 - __bfloat162float(h0), l1 = v1 - __bfloat162float(h1);
    *(uint32_t*)(g_whi + e * 2) = pack2(h0, h1);
    *(uint32_t*)(g_wlo + e * 2) = pack2(__float2bfloat16(l0), __float2bfloat16(l1));
}

// Prepass: split x into bf16 hi/lo (buffer 0).
__global__ void xsplit_kernel(const float* __restrict__ x) {
    size_t e = ((size_t)blockIdx.x * 256u + threadIdx.x) * 2u;
    float2 xv = *(const float2*)(x + e);
    __nv_bfloat16 h0 = __float2bfloat16(xv.x), h1 = __float2bfloat16(xv.y);
    float l0 = xv.x - __bfloat162float(h0), l1 = xv.y - __bfloat162float(h1);
    *(uint32_t*)(g_ahi[0] + e * 2) = pack2(h0, h1);
    *(uint32_t*)(g_alo[0] + e * 2) = pack2(__float2bfloat16(l0), __float2bfloat16(l1));
}

// ---------------------------------------------------------------------------
// Fused wmma GEMM + noise + relu + next-layer split.
// grid (64, 64): n0 = bx*64, m0 = by*64. 128 threads, 4 warps of 32x32.
// ---------------------------------------------------------------------------
__global__ void __launch_bounds__(NTHR, 4)
gemm_tc_kernel(int layer, int abuf, int last,
               const float* __restrict__ z, const float* __restrict__ mu,
               const float* __restrict__ sig, float* __restrict__ out) {
    extern __shared__ __nv_bfloat16 smem[];
    const int tid = threadIdx.x;
    const int wid = tid >> 5;
    const int wm = wid >> 1;          // 0..1  (warp row: 32 rows)
    const int wn = wid & 1;           // 0..1  (warp col: 32 cols)
    const int n0 = blockIdx.x * BN;
    const int m0 = blockIdx.y * BM;

    // ---- per-thread load map: 256 rows x 4 chunks = 1024 slots, 8/thread --
    const char* baseAh = g_ahi[abuf] + (size_t)m0 * NH * 2;
    const char* baseAl = g_alo[abuf] + (size_t)m0 * NH * 2;
    const char* baseWh = g_whi + ((size_t)layer * NH + n0) * NH * 2;
    const char* baseWl = g_wlo + ((size_t)layer * NH + n0) * NH * 2;

    const char* gsrc[8];
    uint32_t    soff[8];
#pragma unroll
    for (int s = 0; s < 8; s++) {
        int idx = tid + s * NTHR;      // 0..1023
        int r = idx >> 2, c = idx & 3; // r: 0..255 across the 4 stacked tiles
        const char* b;
        int sel = r >> 6, row = r & 63;
        b = (sel == 0) ? baseAh : (sel == 1) ? baseAl : (sel == 2) ? baseWh : baseWl;
        gsrc[s] = b + (size_t)row * (NH * 2) + c * 16;
        soff[s] = (uint32_t)(r * LDSR + c * 8);   // regions contiguous: r*LDSR
    }

    auto load_stage = [&](int slot, int kt) {
        __nv_bfloat16* st = smem + slot * STAGE_E;
        const size_t kb = (size_t)kt * 64;  // bytes along K
#pragma unroll
        for (int s = 0; s < 8; s++) cp16(st + soff[s], gsrc[s] + kb);
    };

    wmma::fragment<wmma::accumulator, 16, 16, 16, float> acc[2][2];
#pragma unroll
    for (int i = 0; i < 2; i++)
#pragma unroll
        for (int j = 0; j < 2; j++) wmma::fill_fragment(acc[i][j], 0.0f);

    // Prologue: stage 0.
    load_stage(0, 0); CP_COMMIT();

    for (int kt = 0; kt < NKT; kt++) {
        // R8 order: issue kt+1's loads first (full compute phase to land),
        // then retire group kt, then barrier for cross-thread visibility.
        if (kt + 1 < NKT) load_stage((kt + 1) & 1, kt + 1);
        CP_COMMIT();
        CP_WAIT1();
        __syncthreads();

        const __nv_bfloat16* st  = smem + (kt & 1) * STAGE_E;
        const __nv_bfloat16* sAh = st;
        const __nv_bfloat16* sAl = st + OFF_AL;
        const __nv_bfloat16* sWh = st + OFF_WH;
        const __nv_bfloat16* sWl = st + OFF_WL;

#pragma unroll
        for (int ks = 0; ks < 2; ks++) {
            // Only 12 live fragments: hold everything, let ptxas pipeline.
            wmma::fragment<wmma::matrix_a, 16, 16, 16, __nv_bfloat16, wmma::row_major> aH[2], aL[2];
            wmma::fragment<wmma::matrix_b, 16, 16, 16, __nv_bfloat16, wmma::col_major> bH[2], bL[2];
#pragma unroll
            for (int i = 0; i < 2; i++) {
                const int ro = (wm * 32 + i * 16) * LDSR + ks * 16;
                wmma::load_matrix_sync(aH[i], sAh + ro, LDSR);
                wmma::load_matrix_sync(aL[i], sAl + ro, LDSR);
            }
#pragma unroll
            for (int j = 0; j < 2; j++) {
                const int ro = (wn * 32 + j * 16) * LDSR + ks * 16;
                wmma::load_matrix_sync(bH[j], sWh + ro, LDSR);
                wmma::load_matrix_sync(bL[j], sWl + ro, LDSR);
            }
#pragma unroll
            for (int i = 0; i < 2; i++)
#pragma unroll
                for (int j = 0; j < 2; j++) {
                    wmma::mma_sync(acc[i][j], aH[i], bH[j], acc[i][j]);
                    wmma::mma_sync(acc[i][j], aH[i], bL[j], acc[i][j]);
                    wmma::mma_sync(acc[i][j], aL[i], bH[j], acc[i][j]);
                }
        }
        __syncthreads();   // WAR: buffer (kt+1)&1 reloaded at next iter top
    }

    // ------------------------- epilogue ------------------------------------
    float* fb = (float*)smem;   // 64 x FB_LD fp32 = 17408 B < 40960 B
#pragma unroll
    for (int i = 0; i < 2; i++)
#pragma unroll
        for (int j = 0; j < 2; j++)
            wmma::store_matrix_sync(fb + (wm * 32 + i * 16) * FB_LD + wn * 32 + j * 16,
                                    acc[i][j], FB_LD, wmma::mem_row_major);
    __syncthreads();

    const float* zb = z + (size_t)m0 * NH + n0;
    float* ob = out + (size_t)m0 * (4 * NH) + n0;
    char* nxH = g_ahi[abuf ^ 1];
    char* nxL = g_alo[abuf ^ 1];

#pragma unroll
    for (int it = 0; it < 8; it++) {
        int idx4 = tid + it * NTHR;           // 0..1023 float4 slots
        int row  = idx4 >> 4;                 // 0..63
        int c4   = (idx4 & 15) << 2;          // 0..60

        float4 a  = *(float4*)&fb[row * FB_LD + c4];
        float4 zv = *(const float4*)(zb + (size_t)row * NH + c4);
        float4 mv = *(const float4*)(mu + n0 + c4);
        float4 sv = *(const float4*)(sig + n0 + c4);

        float v0 = fmaxf(a.x + __expf(fmaf(sv.x, zv.x, mv.x)), 0.0f);
        float v1 = fmaxf(a.y + __expf(fmaf(sv.y, zv.y, mv.y)), 0.0f);
        float v2 = fmaxf(a.z + __expf(fmaf(sv.z, zv.z, mv.z)), 0.0f);
        float v3 = fmaxf(a.w + __expf(fmaf(sv.w, zv.w, mv.w)), 0.0f);

        float4 o; o.x = v0; o.y = v1; o.z = v2; o.w = v3;
        *(float4*)(ob + (size_t)row * (4 * NH) + c4) = o;

        if (!last) {
            __nv_bfloat16 h0 = __float2bfloat16(v0), h1 = __float2bfloat16(v1);
            __nv_bfloat16 h2 = __float2bfloat16(v2), h3 = __float2bfloat16(v3);
            float l0 = v0 - __bfloat162float(h0), l1 = v1 - __bfloat162float(h1);
            float l2 = v2 - __bfloat162float(h2), l3 = v3 - __bfloat162float(h3);
            size_t off = ((size_t)(m0 + row) * NH + n0 + c4) * 2;  // bytes
            uint2 ph; ph.x = pack2(h0, h1); ph.y = pack2(h2, h3);
            uint2 pl; pl.x = pack2(__float2bfloat16(l0), __float2bfloat16(l1));
            pl.y = pack2(__float2bfloat16(l2), __float2bfloat16(l3));
            *(uint2*)(nxH + off) = ph;
            *(uint2*)(nxL + off) = pl;
        }
    }
}

// ---------------------------------------------------------------------------
// kernel_launch: prepasses + 4 chained fused GEMMs, graph-capturable.
// Inputs: x, weights, masks, mu, sigma, z. Output float32 [B, 4H].
// ---------------------------------------------------------------------------
extern "C" void kernel_launch(void* const* d_in, const int* in_sizes, int n_in,
                              void* d_out, int out_size) {
    const float* x   = (const float*)d_in[0];
    const float* w   = (const float*)d_in[1];
    const float* mk  = (const float*)d_in[2];
    const float* mu  = (const float*)d_in[3];
    const float* sg  = (const float*)d_in[4];
    const float* z   = (const float*)d_in[5];
    float*       out = (float*)d_out;

    cudaFuncSetAttribute(gemm_tc_kernel,
                         cudaFuncAttributeMaxDynamicSharedMemorySize, SMEM_BYTES);

    {   // W split
        unsigned blocks = (unsigned)(((size_t)NL * NH * NH / 2) / 256);
        wsplit_kernel<<<blocks, 256>>>(w, mk);
    }
    {   // x split
        unsigned blocks = (unsigned)(((size_t)NB * NH / 2) / 256);
        xsplit_kernel<<<blocks, 256>>>(x);
    }

    dim3 grid(NH / BN, NB / BM);  // (64, 64)
    for (int l = 0; l < NL; l++) {
        gemm_tc_kernel<<<grid, NTHR, SMEM_BYTES>>>(
            l, l & 1, (l == NL - 1) ? 1 : 0,
            z + (size_t)l * NB * NH,
            mu + (size_t)l * NH,
            sg + (size_t)l * NH,
            out + (size_t)l * NH);
    }
}